// round 15
// baseline (speedup 1.0000x reference)
#include <cuda_runtime.h>

#define WS 8
#define BB 64
#define TT 256
#define HH 64
#define NW 248

typedef unsigned long long u64;

__device__ __forceinline__ void fma2(u64 &acc, u64 a, u64 b) {
    asm("fma.rn.f32x2 %0, %1, %2, %0;" : "+l"(acc) : "l"(a), "l"(b));
}
__device__ __forceinline__ void add2(u64 &a, u64 b) {
    asm("add.rn.f32x2 %0, %1, %2;" : "=l"(a) : "l"(a), "l"(b));
}
__device__ __forceinline__ u64 pack2(float a, float b) {
    u64 r; asm("mov.b64 %0, {%1, %2};" : "=l"(r) : "f"(a), "f"(b)); return r;
}
__device__ __forceinline__ float lo_f(u64 v) { return __uint_as_float((unsigned)v); }
__device__ __forceinline__ float hi_f(u64 v) { return __uint_as_float((unsigned)(v >> 32)); }
__device__ __forceinline__ float hsum(u64 v) { return lo_f(v) + hi_f(v); }
__device__ __forceinline__ float tanh_ap(float x) {
    float y; asm("tanh.approx.f32 %0, %1;" : "=f"(y) : "f"(x)); return y;
}
__device__ __forceinline__ u64 shflx(u64 v, int mask) {
    unsigned lo = (unsigned)v, hi = (unsigned)(v >> 32);
    lo = __shfl_xor_sync(0xffffffffu, lo, mask);
    hi = __shfl_xor_sync(0xffffffffu, hi, mask);
    return ((u64)hi << 32) | lo;
}
// gather gates into lane 0 of each 4-lane group; c/h valid in lane 0 only
__device__ __forceinline__ float cell_from_act(float act, float &c, bool first) {
    float f_ = __shfl_down_sync(0xffffffffu, act, 1);
    float g_ = __shfl_down_sync(0xffffffffu, act, 2);
    float o_ = __shfl_down_sync(0xffffffffu, act, 3);
    c = first ? act * g_ : fmaf(f_, c, act * g_);
    return o_ * tanh_ap(c);
}

__device__ __forceinline__ float xin_value(const float* trajs, const float* preds,
                                           int w, int s, int f) {
    if (w == 0) return trajs[s * 4 + f];
    if (w < WS) {
        if (s < WS - w) return trajs[(w + s) * 4 + f];
        return (f < 2) ? trajs[(2 * w + s - 1) * 4 + f]
                       : preds[(w + s - WS) * 2 + (f - 2)];
    }
    return (f < 2) ? trajs[(w + s) * 4 + f]
                   : preds[(w + s - WS) * 2 + (f - 2)];
}

__global__ __launch_bounds__(256, 1)
void or_lstm_kernel(const float* __restrict__ traj,
                    const float* __restrict__ Wih0, const float* __restrict__ Whh0,
                    const float* __restrict__ bih0, const float* __restrict__ bhh0,
                    const float* __restrict__ Wih1, const float* __restrict__ Whh1,
                    const float* __restrict__ bih1, const float* __restrict__ bhh1,
                    const float* __restrict__ Wlin, const float* __restrict__ blin,
                    float* __restrict__ out)
{
    const int b    = blockIdx.x;
    const int tid  = threadIdx.x;
    const int m    = tid >> 2;
    const int q    = tid & 3;       // own gate index (i,f,g,o)
    const int p    = q >> 1;        // gate pair: 0 -> (i,f), 1 -> (g,o)
    const int j    = q & 1;         // k-half: [32j, 32j+32)
    const int wid  = tid >> 5;
    const int lane = tid & 31;

    __shared__ __align__(16) float trajs[TT * 4];
    __shared__ __align__(16) float h0s[2][HH], h1s[2][HH];
    __shared__ __align__(16) float xinb[2][WS][4];   // [window parity][s][feature]
    __shared__ float preds[NW * 2];
    __shared__ float predpart[16];
    __shared__ float blin_s[2];

    for (int i = tid; i < TT * 4; i += 256) trajs[i] = traj[b * TT * 4 + i];
    if (tid < 2) blin_s[tid] = blin[tid];

    // ---- weights -> registers: thread (m,q) owns gates {2p, 2p+1}, k-half j ----
    u64 whh0p[2][16], wih1p[2][16], whh1p[2][16];
    #pragma unroll
    for (int e = 0; e < 2; e++) {
        const int rg = 64 * (2 * p + e) + m;
        const ulonglong2* s0 = (const ulonglong2*)(Whh0 + rg * HH + 32 * j);
        const ulonglong2* s1 = (const ulonglong2*)(Wih1 + rg * HH + 32 * j);
        const ulonglong2* s2 = (const ulonglong2*)(Whh1 + rg * HH + 32 * j);
        #pragma unroll
        for (int cc = 0; cc < 8; cc++) {
            ulonglong2 v0 = s0[cc]; whh0p[e][2 * cc] = v0.x; whh0p[e][2 * cc + 1] = v0.y;
            ulonglong2 v1 = s1[cc]; wih1p[e][2 * cc] = v1.x; wih1p[e][2 * cc + 1] = v1.y;
            ulonglong2 v2 = s2[cc]; whh1p[e][2 * cc] = v2.x; whh1p[e][2 * cc + 1] = v2.y;
        }
    }
    // own-gate (= q) private data
    const int og = 64 * q + m;
    const float4 wx   = *(const float4*)(Wih0 + og * 4);
    const float  b0f  = bih0[og] + bhh0[og];
    const float  b1f  = bih1[og] + bhh1[og];
    const float wlreg = (q < 2) ? Wlin[q * 64 + m] : 0.0f;
    const float km = (q == 2) ? 1.0f : 0.5f;
    const float kb = (q == 2) ? 0.0f : 0.5f;

    float c0 = 0.f, c1 = 0.f, h0v = 0.f, h1v = 0.f;

    // own-gate x-term: b0 + Wih0[og]·x(s) — phase-top, off the critical chain
    auto xsum = [&](int pi, int s) -> float {
        float4 xv = *(const float4*)&xinb[pi][s][0];
        float r = fmaf(wx.x, xv.x, b0f);
        r = fmaf(wx.y, xv.y, r);
        r = fmaf(wx.z, xv.z, r);
        return fmaf(wx.w, xv.w, r);
    };
    // reduce own k-half pair partials across j (ONE u64 shfl round), pick gate q
    auto pair_total = [&](u64 aA0, u64 aB0, u64 aA1, u64 aB1) -> float {
        add2(aA0, aB0); add2(aA1, aB1);
        u64 P = pack2(hsum(aA0), hsum(aA1));   // (gate 2p, gate 2p+1) half-partials
        add2(P, shflx(P, 1));                  // sum the two k-halves
        return j ? hi_f(P) : lo_f(P);          // own gate = 2p + j = q
    };
    // heavy step s = 1..7: dots, then P0 epilogue first, then P1
    auto step = [&](int s, float xs) {
        u64 z0[2] = {0,0}, z1[2] = {0,0};   // layer-0 accs (gate e, 2-way split)
        u64 y0[2] = {0,0}, y1[2] = {0,0};   // layer-1 accs
        const float* h0p = h0s[(s - 1) & 1] + 32 * j;
        #pragma unroll
        for (int cc = 0; cc < 8; cc++) {
            ulonglong2 hv = ((const ulonglong2*)h0p)[cc];
            u64* z = (cc & 1) ? z1 : z0;
            u64* y = (cc & 1) ? y1 : y0;
            #pragma unroll
            for (int e = 0; e < 2; e++) {
                fma2(z[e], hv.x, whh0p[e][2 * cc]); fma2(z[e], hv.y, whh0p[e][2 * cc + 1]);
                fma2(y[e], hv.x, wih1p[e][2 * cc]); fma2(y[e], hv.y, wih1p[e][2 * cc + 1]);
            }
        }
        if (s > 1) {   // P1(s-1) h1 term: h1(s-2) at parity s&1
            const float* h1p = h1s[s & 1] + 32 * j;
            #pragma unroll
            for (int cc = 0; cc < 8; cc++) {
                ulonglong2 hv = ((const ulonglong2*)h1p)[cc];
                u64* y = (cc & 1) ? y1 : y0;
                #pragma unroll
                for (int e = 0; e < 2; e++) {
                    fma2(y[e], hv.x, whh1p[e][2 * cc]); fma2(y[e], hv.y, whh1p[e][2 * cc + 1]);
                }
            }
        }
        // P0(s) epilogue FIRST
        float arg0 = pair_total(z0[0], z1[0], z0[1], z1[1]) + xs;
        h0v = cell_from_act(fmaf(km, tanh_ap(km * arg0), kb), c0, false);
        if (q == 0) h0s[s & 1][m] = h0v;
        // P1(s-1) epilogue
        float arg1 = pair_total(y0[0], y1[0], y0[1], y1[1]) + b1f;
        h1v = cell_from_act(fmaf(km, tanh_ap(km * arg1), kb), c1, s == 1);
        if (q == 0) h1s[(s - 1) & 1][m] = h1v;
    };
    // P1(7) of previous window + Wlin·h1 partial
    auto p1_last = [&]() {
        u64 y0[2] = {0,0}, y1[2] = {0,0};
        const float* h0p = h0s[1] + 32 * j;
        const float* h1p = h1s[0] + 32 * j;
        #pragma unroll
        for (int cc = 0; cc < 8; cc++) {
            ulonglong2 hv = ((const ulonglong2*)h0p)[cc];
            ulonglong2 gv = ((const ulonglong2*)h1p)[cc];
            u64* y = (cc & 1) ? y1 : y0;
            #pragma unroll
            for (int e = 0; e < 2; e++) {
                fma2(y[e], hv.x, wih1p[e][2 * cc]); fma2(y[e], hv.y, wih1p[e][2 * cc + 1]);
                fma2(y[e], gv.x, whh1p[e][2 * cc]); fma2(y[e], gv.y, whh1p[e][2 * cc + 1]);
            }
        }
        float arg1 = pair_total(y0[0], y1[0], y0[1], y1[1]) + b1f;
        h1v = cell_from_act(fmaf(km, tanh_ap(km * arg1), kb), c1, false);
        float hb = __shfl_sync(0xffffffffu, h1v, lane & ~3);
        float pv = wlreg * hb;
        pv += __shfl_xor_sync(0xffffffffu, pv, 4);
        pv += __shfl_xor_sync(0xffffffffu, pv, 8);
        pv += __shfl_xor_sync(0xffffffffu, pv, 16);
        if (lane < 2) predpart[wid * 2 + lane] = pv;
    };

    __syncthreads();                 // staging done
    if (tid < 32) {                  // xin window 0 (pure traj)
        const int s = tid >> 2, f = tid & 3;
        xinb[0][s][f] = xin_value(trajs, preds, 0, s, f);
    }
    __syncthreads();

    for (int w = 0; w < NW; w++) {
        const int pw = w & 1;

        // ===== phase A: P1(7, w-1) + predpart + P0(0, w); side: xin rows 0..5 of w+1
        {
            float xs0 = xsum(pw, 0);             // off-chain
            if (w > 0) p1_last();
            h0v = cell_from_act(fmaf(km, tanh_ap(km * xs0), kb), c0, true);
            if (q == 0) h0s[0][m] = h0v;
            if (wid == 5 && lane < 24 && (w + 1) < NW) {
                const int s = lane >> 2, f = lane & 3;
                xinb[pw ^ 1][s][f] = xin_value(trajs, preds, w + 1, s, f);
            }
        }
        __syncthreads();

        // ===== phase B: P1(0) + P0(1); side: warp6 finalizes pred[w-1]
        {
            float xs = xsum(pw, 1);
            step(1, xs);
            if (w > 0 && wid == 6 && lane < 2) {
                float d = blin_s[lane];
                #pragma unroll
                for (int k = 0; k < 8; k++) d += predpart[k * 2 + lane];
                const float prev = (w == 1) ? trajs[7 * 4 + 2 + lane]
                                            : preds[(w - 2) * 2 + lane];
                const float pr = prev + d;
                preds[(w - 1) * 2 + lane] = pr;
                out[(b * NW + (w - 1)) * 2 + lane] = pr;
            }
        }
        __syncthreads();

        // ===== phases C..H: s = 2..7; C has tiny xin side (8 lanes of warp 7)
        #pragma unroll 2
        for (int s = 2; s < WS; s++) {
            float xs = xsum(pw, s);
            step(s, xs);
            if (s == 2 && wid == 7 && lane < 8) {
                if (lane < 4)
                    xinb[pw][7][lane] = xin_value(trajs, preds, w, 7, lane);
                else if ((w + 1) < NW)
                    xinb[pw ^ 1][6][lane - 4] =
                        xin_value(trajs, preds, w + 1, 6, lane - 4);
            }
            __syncthreads();
        }
    }

    // ===== tail: P1(7, NW-1) + predpart, then finalize pred[NW-1] =====
    p1_last();
    __syncthreads();
    if (tid < 2) {
        float d = blin_s[tid];
        #pragma unroll
        for (int k = 0; k < 8; k++) d += predpart[k * 2 + tid];
        out[(b * NW + (NW - 1)) * 2 + tid] = preds[(NW - 2) * 2 + tid] + d;
    }
    // ---- final states: h[2,B,H] then c[2,B,H] (valid in q==0 lanes) ----
    if (q == 0) {
        const int base = BB * NW * 2;
        out[base + 0 * BB * HH + b * HH + m] = h0v;
        out[base + 1 * BB * HH + b * HH + m] = h1v;
        out[base + 2 * BB * HH + b * HH + m] = c0;
        out[base + 3 * BB * HH + b * HH + m] = c1;
    }
}

extern "C" void kernel_launch(void* const* d_in, const int* in_sizes, int n_in,
                              void* d_out, int out_size) {
    const float* traj = (const float*)d_in[0];
    const float* Wih0 = (const float*)d_in[1];
    const float* Whh0 = (const float*)d_in[2];
    const float* bih0 = (const float*)d_in[3];
    const float* bhh0 = (const float*)d_in[4];
    const float* Wih1 = (const float*)d_in[5];
    const float* Whh1 = (const float*)d_in[6];
    const float* bih1 = (const float*)d_in[7];
    const float* bhh1 = (const float*)d_in[8];
    const float* Wlin = (const float*)d_in[9];
    const float* blin = (const float*)d_in[10];

    or_lstm_kernel<<<BB, 256>>>(traj, Wih0, Whh0, bih0, bhh0,
                                Wih1, Whh1, bih1, bhh1,
                                Wlin, blin, (float*)d_out);
}

// round 16
// speedup vs baseline: 1.0396x; 1.0396x over previous
#include <cuda_runtime.h>

#define WS 8
#define BB 64
#define TT 256
#define HH 64
#define NW 248

typedef unsigned long long u64;

__device__ __forceinline__ void fma2(u64 &acc, u64 a, u64 b) {
    asm("fma.rn.f32x2 %0, %1, %2, %0;" : "+l"(acc) : "l"(a), "l"(b));
}
__device__ __forceinline__ void add2(u64 &a, u64 b) {
    asm("add.rn.f32x2 %0, %1, %2;" : "=l"(a) : "l"(a), "l"(b));
}
__device__ __forceinline__ u64 pack2(float a, float b) {
    u64 r; asm("mov.b64 %0, {%1, %2};" : "=l"(r) : "f"(a), "f"(b)); return r;
}
__device__ __forceinline__ float lo_f(u64 v) { return __uint_as_float((unsigned)v); }
__device__ __forceinline__ float hi_f(u64 v) { return __uint_as_float((unsigned)(v >> 32)); }
__device__ __forceinline__ float hsum(u64 v) { return lo_f(v) + hi_f(v); }
__device__ __forceinline__ float tanh_ap(float x) {
    float y; asm("tanh.approx.f32 %0, %1;" : "=f"(y) : "f"(x)); return y;
}
__device__ __forceinline__ u64 shflx(u64 v, int mask) {
    unsigned lo = (unsigned)v, hi = (unsigned)(v >> 32);
    lo = __shfl_xor_sync(0xffffffffu, lo, mask);
    hi = __shfl_xor_sync(0xffffffffu, hi, mask);
    return ((u64)hi << 32) | lo;
}
__device__ __forceinline__ u64 reduce_pair(u64 v) {
    add2(v, shflx(v, 1)); add2(v, shflx(v, 2)); return v;
}
// lane sl's own-gate element out of the packed (g0,g1)/(g2,g3) totals
__device__ __forceinline__ float selown(u64 A, u64 B, int sl) {
    return (sl & 2) ? ((sl & 1) ? hi_f(B) : lo_f(B))
                    : ((sl & 1) ? hi_f(A) : lo_f(A));
}
// gather gates into lane 0 of each 4-lane group; c/h valid in lane 0 only
__device__ __forceinline__ float cell_from_act(float act, float &c, bool first) {
    float f_ = __shfl_down_sync(0xffffffffu, act, 1);
    float g_ = __shfl_down_sync(0xffffffffu, act, 2);
    float o_ = __shfl_down_sync(0xffffffffu, act, 3);
    c = first ? act * g_ : fmaf(f_, c, act * g_);
    return o_ * tanh_ap(c);
}

__device__ __forceinline__ float xin_value(const float* trajs, const float* preds,
                                           int w, int s, int f) {
    if (w == 0) return trajs[s * 4 + f];
    if (w < WS) {
        if (s < WS - w) return trajs[(w + s) * 4 + f];
        return (f < 2) ? trajs[(2 * w + s - 1) * 4 + f]
                       : preds[(w + s - WS) * 2 + (f - 2)];
    }
    return (f < 2) ? trajs[(w + s) * 4 + f]
                   : preds[(w + s - WS) * 2 + (f - 2)];
}

__global__ __launch_bounds__(256, 1)
void or_lstm_kernel(const float* __restrict__ traj,
                    const float* __restrict__ Wih0, const float* __restrict__ Whh0,
                    const float* __restrict__ bih0, const float* __restrict__ bhh0,
                    const float* __restrict__ Wih1, const float* __restrict__ Whh1,
                    const float* __restrict__ bih1, const float* __restrict__ bhh1,
                    const float* __restrict__ Wlin, const float* __restrict__ blin,
                    float* __restrict__ out)
{
    const int b    = blockIdx.x;
    const int tid  = threadIdx.x;
    const int m    = tid >> 2;
    const int sl   = tid & 3;
    const int wid  = tid >> 5;
    const int lane = tid & 31;

    __shared__ __align__(16) float trajs[TT * 4];
    __shared__ __align__(16) float h0s[2][HH], h1s[2][HH];
    __shared__ __align__(16) float h0z0[HH];   // h0(0) of current window
    __shared__ __align__(16) float h0z7[HH];   // h0(7) of previous window
    __shared__ __align__(16) float h1z[HH];    // h1(0) of current window
    __shared__ __align__(16) float xinb[2][WS][4];
    __shared__ float preds[NW * 2];
    __shared__ float predpart[16];
    __shared__ float blin_s[2];

    for (int i = tid; i < TT * 4; i += 256) trajs[i] = traj[b * TT * 4 + i];
    if (tid < 2) blin_s[tid] = blin[tid];

    // ---- weights -> registers (thread (m,sl): 4 gate rows, 16-k slice) ----
    u64 whh0p[4][4][2], wih1p[4][4][2], whh1p[4][4][2];
    #pragma unroll
    for (int g = 0; g < 4; g++) {
        const int rg = 64 * g + m;
        #pragma unroll
        for (int c = 0; c < 4; c++) {
            const int k0 = 16 * c + 4 * sl;
            ulonglong2 v0 = *(const ulonglong2*)(Whh0 + rg * HH + k0);
            whh0p[g][c][0] = v0.x; whh0p[g][c][1] = v0.y;
            ulonglong2 v1 = *(const ulonglong2*)(Wih1 + rg * HH + k0);
            wih1p[g][c][0] = v1.x; wih1p[g][c][1] = v1.y;
            ulonglong2 v2 = *(const ulonglong2*)(Whh1 + rg * HH + k0);
            whh1p[g][c][0] = v2.x; whh1p[g][c][1] = v2.y;
        }
    }
    // own-gate (= sl) private data
    const int og = 64 * sl + m;
    const float4 wx   = *(const float4*)(Wih0 + og * 4);
    const float  b0f  = bih0[og] + bhh0[og];
    const float  b1f  = bih1[og] + bhh1[og];
    const float wlreg = (sl < 2) ? Wlin[sl * 64 + m] : 0.0f;
    const float km = (sl == 2) ? 1.0f : 0.5f;
    const float kb = (sl == 2) ? 0.0f : 0.5f;

    float c0 = 0.f, c1 = 0.f, h0v = 0.f, h1v = 0.f;

    auto xsum = [&](int pi, int s) -> float {
        float4 xv = *(const float4*)&xinb[pi][s][0];
        float r = fmaf(wx.x, xv.x, b0f);
        r = fmaf(wx.y, xv.y, r);
        r = fmaf(wx.z, xv.z, r);
        return fmaf(wx.w, xv.w, r);
    };
    // heavy step s = 1..7: dual dot over h0(s-1), + h1(s-2) dot for s>1.
    // h0prev / h1prev passed explicitly (slot remap); stores routed per s.
    auto step = [&](int s, float xs, const float* h0prev, const float* h1prev) {
        u64 a1[4] = {0,0,0,0}, a0[4] = {0,0,0,0};
        #pragma unroll
        for (int c = 0; c < 4; c++) {
            ulonglong2 hv = *(const ulonglong2*)(h0prev + 16 * c + 4 * sl);
            #pragma unroll
            for (int g = 0; g < 4; g++) {
                fma2(a0[g], hv.x, whh0p[g][c][0]); fma2(a0[g], hv.y, whh0p[g][c][1]);
                fma2(a1[g], hv.x, wih1p[g][c][0]); fma2(a1[g], hv.y, wih1p[g][c][1]);
            }
        }
        if (s > 1) {
            #pragma unroll
            for (int c = 0; c < 4; c++) {
                ulonglong2 hv = *(const ulonglong2*)(h1prev + 16 * c + 4 * sl);
                #pragma unroll
                for (int g = 0; g < 4; g++) {
                    fma2(a1[g], hv.x, whh1p[g][c][0]); fma2(a1[g], hv.y, whh1p[g][c][1]);
                }
            }
        }
        // P0(s) epilogue FIRST
        u64 A0 = reduce_pair(pack2(hsum(a0[0]), hsum(a0[1])));
        u64 B0 = reduce_pair(pack2(hsum(a0[2]), hsum(a0[3])));
        float arg0 = selown(A0, B0, sl) + xs;
        h0v = cell_from_act(fmaf(km, tanh_ap(km * arg0), kb), c0, false);
        if (sl == 0) { if (s == 7) h0z7[m] = h0v; else h0s[s & 1][m] = h0v; }
        // P1(s-1) epilogue
        u64 A1 = reduce_pair(pack2(hsum(a1[0]), hsum(a1[1])));
        u64 B1 = reduce_pair(pack2(hsum(a1[2]), hsum(a1[3])));
        float arg1 = selown(A1, B1, sl) + b1f;
        h1v = cell_from_act(fmaf(km, tanh_ap(km * arg1), kb), c1, s == 1);
        if (sl == 0) { if (s == 1) h1z[m] = h1v; else h1s[(s - 1) & 1][m] = h1v; }
    };
    // P1(7) of previous window (reads h0z7 + h1(6)=h1s[0]) + Wlin partial
    auto p1_last = [&]() {
        u64 a1[4] = {0,0,0,0};
        #pragma unroll
        for (int c = 0; c < 4; c++) {
            ulonglong2 hv = *(const ulonglong2*)(h0z7 + 16 * c + 4 * sl);
            ulonglong2 gv = *(const ulonglong2*)(h1s[0] + 16 * c + 4 * sl);
            #pragma unroll
            for (int g = 0; g < 4; g++) {
                fma2(a1[g], hv.x, wih1p[g][c][0]); fma2(a1[g], hv.y, wih1p[g][c][1]);
                fma2(a1[g], gv.x, whh1p[g][c][0]); fma2(a1[g], gv.y, whh1p[g][c][1]);
            }
        }
        u64 A1 = reduce_pair(pack2(hsum(a1[0]), hsum(a1[1])));
        u64 B1 = reduce_pair(pack2(hsum(a1[2]), hsum(a1[3])));
        float arg1 = selown(A1, B1, sl) + b1f;
        h1v = cell_from_act(fmaf(km, tanh_ap(km * arg1), kb), c1, false);
        float hb = __shfl_sync(0xffffffffu, h1v, lane & ~3);
        float pv = wlreg * hb;
        pv += __shfl_xor_sync(0xffffffffu, pv, 4);
        pv += __shfl_xor_sync(0xffffffffu, pv, 8);
        pv += __shfl_xor_sync(0xffffffffu, pv, 16);
        if (lane < 2) predpart[wid * 2 + lane] = pv;
    };

    __syncthreads();                 // staging done
    if (tid < 32) {                  // xin window 0 (pure traj)
        const int s = tid >> 2, f = tid & 3;
        xinb[0][s][f] = xin_value(trajs, preds, 0, s, f);
    }
    __syncthreads();

    // ===== prologue: P0(0, 0) -> h0z0 =====
    {
        float xs0 = xsum(0, 0);
        h0v = cell_from_act(fmaf(km, tanh_ap(km * xs0), kb), c0, true);
        if (sl == 0) h0z0[m] = h0v;
    }
    __syncthreads();

    for (int w = 0; w < NW; w++) {
        const int pw = w & 1;

        // ===== φ1: [P1(7,w-1) + predpart] + [P1(0,w) + P0(1,w)]
        {
            float xs = xsum(pw, 1);
            if (w > 0) p1_last();            // uses old c1, then step reinits it
            step(1, xs, h0z0, h0z0 /*unused*/);
        }
        __syncthreads();

        // ===== φ2: P1(1)+P0(2); side: warp6 finalizes pred[w-1]
        {
            float xs = xsum(pw, 2);
            step(2, xs, h0s[1], h1z);        // h0(1), h1(0)
            if (w > 0 && wid == 6 && lane < 2) {
                float d = blin_s[lane];
                #pragma unroll
                for (int k = 0; k < 8; k++) d += predpart[k * 2 + lane];
                const float prev = (w == 1) ? trajs[7 * 4 + 2 + lane]
                                            : preds[(w - 2) * 2 + lane];
                const float pr = prev + d;
                preds[(w - 1) * 2 + lane] = pr;
                out[(b * NW + (w - 1)) * 2 + lane] = pr;
            }
        }
        __syncthreads();

        // ===== φ3: P1(2)+P0(3); side: xin row7(w) + row6(w+1) (warp7, 8 lanes)
        {
            float xs = xsum(pw, 3);
            step(3, xs, h0s[0], h1s[1]);     // h0(2), h1(1)
            if (wid == 7 && lane < 8) {
                if (lane < 4)
                    xinb[pw][7][lane] = xin_value(trajs, preds, w, 7, lane);
                else if ((w + 1) < NW)
                    xinb[pw ^ 1][6][lane - 4] =
                        xin_value(trajs, preds, w + 1, 6, lane - 4);
            }
        }
        __syncthreads();

        // ===== φ4: P1(3)+P0(4); side: xin rows 0..5 of w+1 (warp5, 24 lanes)
        {
            float xs = xsum(pw, 4);
            step(4, xs, h0s[1], h1s[0]);     // h0(3), h1(2)
            if (wid == 5 && lane < 24 && (w + 1) < NW) {
                const int s = lane >> 2, f = lane & 3;
                xinb[pw ^ 1][s][f] = xin_value(trajs, preds, w + 1, s, f);
            }
        }
        __syncthreads();

        // ===== φ5: P1(4)+P0(5)
        {
            float xs = xsum(pw, 5);
            step(5, xs, h0s[0], h1s[1]);     // h0(4), h1(3)
        }
        __syncthreads();

        // ===== φ6: P1(5)+P0(6)
        {
            float xs = xsum(pw, 6);
            step(6, xs, h0s[1], h1s[0]);     // h0(5), h1(4)
        }
        __syncthreads();

        // ===== φ7: P1(6)+P0(7) [+ P0(0, w+1) -> h0z0]
        {
            float xs  = xsum(pw, 7);
            float xs0 = ((w + 1) < NW) ? xsum(pw ^ 1, 0) : 0.0f;
            step(7, xs, h0s[0], h1s[1]);     // h0(6), h1(5); stores h0z7, h1s[0]
            if ((w + 1) < NW) {
                float hz = cell_from_act(fmaf(km, tanh_ap(km * xs0), kb), c0, true);
                if (sl == 0) h0z0[m] = hz;
                h0v = hz;
            }
        }
        __syncthreads();
    }

    // ===== tail: P1(7, NW-1) + predpart, then finalize pred[NW-1] =====
    p1_last();
    __syncthreads();
    if (tid < 2) {
        float d = blin_s[tid];
        #pragma unroll
        for (int k = 0; k < 8; k++) d += predpart[k * 2 + tid];
        out[(b * NW + (NW - 1)) * 2 + tid] = preds[(NW - 2) * 2 + tid] + d;
    }
    // ---- final states: h[2,B,H] then c[2,B,H] (valid in sl==0 lanes) ----
    if (sl == 0) {
        const int base = BB * NW * 2;
        out[base + 0 * BB * HH + b * HH + m] = h0v;   // h0(7, NW-1)
        out[base + 1 * BB * HH + b * HH + m] = h1v;   // h1(7, NW-1)
        out[base + 2 * BB * HH + b * HH + m] = c0;
        out[base + 3 * BB * HH + b * HH + m] = c1;
    }
}

extern "C" void kernel_launch(void* const* d_in, const int* in_sizes, int n_in,
                              void* d_out, int out_size) {
    const float* traj = (const float*)d_in[0];
    const float* Wih0 = (const float*)d_in[1];
    const float* Whh0 = (const float*)d_in[2];
    const float* bih0 = (const float*)d_in[3];
    const float* bhh0 = (const float*)d_in[4];
    const float* Wih1 = (const float*)d_in[5];
    const float* Whh1 = (const float*)d_in[6];
    const float* bih1 = (const float*)d_in[7];
    const float* bhh1 = (const float*)d_in[8];
    const float* Wlin = (const float*)d_in[9];
    const float* blin = (const float*)d_in[10];

    or_lstm_kernel<<<BB, 256>>>(traj, Wih0, Whh0, bih0, bhh0,
                                Wih1, Whh1, bih1, bhh1,
                                Wlin, blin, (float*)d_out);
}

// round 17
// speedup vs baseline: 1.0879x; 1.0465x over previous
#include <cuda_runtime.h>

#define WS 8
#define BB 64
#define TT 256
#define HH 64
#define NW 248

typedef unsigned long long u64;

__device__ __forceinline__ void fma2(u64 &acc, u64 a, u64 b) {
    asm("fma.rn.f32x2 %0, %1, %2, %0;" : "+l"(acc) : "l"(a), "l"(b));
}
__device__ __forceinline__ void add2(u64 &a, u64 b) {
    asm("add.rn.f32x2 %0, %1, %2;" : "=l"(a) : "l"(a), "l"(b));
}
__device__ __forceinline__ u64 mul2c(u64 a, u64 b) {
    u64 r; asm("mul.rn.f32x2 %0, %1, %2;" : "=l"(r) : "l"(a), "l"(b)); return r;
}
__device__ __forceinline__ u64 pack2(float a, float b) {
    u64 r; asm("mov.b64 %0, {%1, %2};" : "=l"(r) : "f"(a), "f"(b)); return r;
}
__device__ __forceinline__ float lo_f(u64 v) { return __uint_as_float((unsigned)v); }
__device__ __forceinline__ float hi_f(u64 v) { return __uint_as_float((unsigned)(v >> 32)); }
__device__ __forceinline__ float hsum(u64 v) { return lo_f(v) + hi_f(v); }
__device__ __forceinline__ float tanh_ap(float x) {
    float y; asm("tanh.approx.f32 %0, %1;" : "=f"(y) : "f"(x)); return y;
}
__device__ __forceinline__ u64 shflx(u64 v, int mask) {
    unsigned lo = (unsigned)v, hi = (unsigned)(v >> 32);
    lo = __shfl_xor_sync(0xffffffffu, lo, mask);
    hi = __shfl_xor_sync(0xffffffffu, hi, mask);
    return ((u64)hi << 32) | lo;
}
// Asymmetric 4-lane reduce: lane sl returns the TOTAL of gate sl (3 SHFL.32).
__device__ __forceinline__ float red4(u64 a0, u64 a1, u64 a2, u64 a3, int sl) {
    u64 P = pack2(hsum(a0), hsum(a1));        // (g0, g1) partials
    u64 Q = pack2(hsum(a2), hsum(a3));        // (g2, g3) partials
    u64 send = (sl & 2) ? P : Q;              // ship the pair the partner owns
    u64 recv = shflx(send, 2);
    u64 R = (sl & 2) ? Q : P;
    add2(R, recv);                            // lanes 0,1: (g0,g1); lanes 2,3: (g2,g3)
    float send2 = (sl & 1) ? lo_f(R) : hi_f(R);
    float recv2 = __shfl_xor_sync(0xffffffffu, send2, 1);
    float keep  = (sl & 1) ? hi_f(R) : lo_f(R);
    return keep + recv2;                      // gate sl total
}
// gather gates into lane 0 of each 4-lane group; c/h valid in lane 0 only
__device__ __forceinline__ float cell_from_act(float act, float &c, bool first) {
    float f_ = __shfl_down_sync(0xffffffffu, act, 1);
    float g_ = __shfl_down_sync(0xffffffffu, act, 2);
    float o_ = __shfl_down_sync(0xffffffffu, act, 3);
    c = first ? act * g_ : fmaf(f_, c, act * g_);
    return o_ * tanh_ap(c);
}

__device__ __forceinline__ float xin_value(const float* trajs, const float* preds,
                                           int w, int s, int f) {
    if (w == 0) return trajs[s * 4 + f];
    if (w < WS) {
        if (s < WS - w) return trajs[(w + s) * 4 + f];
        return (f < 2) ? trajs[(2 * w + s - 1) * 4 + f]
                       : preds[(w + s - WS) * 2 + (f - 2)];
    }
    return (f < 2) ? trajs[(w + s) * 4 + f]
                   : preds[(w + s - WS) * 2 + (f - 2)];
}

__global__ __launch_bounds__(256, 1)
void or_lstm_kernel(const float* __restrict__ traj,
                    const float* __restrict__ Wih0, const float* __restrict__ Whh0,
                    const float* __restrict__ bih0, const float* __restrict__ bhh0,
                    const float* __restrict__ Wih1, const float* __restrict__ Whh1,
                    const float* __restrict__ bih1, const float* __restrict__ bhh1,
                    const float* __restrict__ Wlin, const float* __restrict__ blin,
                    float* __restrict__ out)
{
    const int b    = blockIdx.x;
    const int tid  = threadIdx.x;
    const int m    = tid >> 2;
    const int sl   = tid & 3;
    const int wid  = tid >> 5;
    const int lane = tid & 31;

    __shared__ __align__(16) float trajs[TT * 4];
    __shared__ __align__(16) float h0s[2][HH], h1s[2][HH];
    __shared__ __align__(16) float h0z0[HH];   // h0(0) of current window
    __shared__ __align__(16) float h0z7[HH];   // h0(7) of previous window
    __shared__ __align__(16) float h1z[HH];    // h1(0) of current window
    __shared__ __align__(16) float xinb[2][WS][4];
    __shared__ float preds[NW * 2];
    __shared__ float predpart[16];
    __shared__ float blin_s[2];

    for (int i = tid; i < TT * 4; i += 256) trajs[i] = traj[b * TT * 4 + i];
    if (tid < 2) blin_s[tid] = blin[tid];

    // ---- weights -> registers, PRE-SCALED by gate (0.5 for i,f,o; 1.0 for g) ----
    // Folding the sigmoid half-scale into the weights removes the km* multiply
    // from the critical MUFU chain: act = fma(km, tanh(arg), kb) directly.
    u64 whh0p[4][4][2], wih1p[4][4][2], whh1p[4][4][2];
    #pragma unroll
    for (int g = 0; g < 4; g++) {
        const int rg = 64 * g + m;
        const float sg = (g == 2) ? 1.0f : 0.5f;
        const u64 sg2 = pack2(sg, sg);
        #pragma unroll
        for (int c = 0; c < 4; c++) {
            const int k0 = 16 * c + 4 * sl;
            ulonglong2 v0 = *(const ulonglong2*)(Whh0 + rg * HH + k0);
            whh0p[g][c][0] = mul2c(v0.x, sg2); whh0p[g][c][1] = mul2c(v0.y, sg2);
            ulonglong2 v1 = *(const ulonglong2*)(Wih1 + rg * HH + k0);
            wih1p[g][c][0] = mul2c(v1.x, sg2); wih1p[g][c][1] = mul2c(v1.y, sg2);
            ulonglong2 v2 = *(const ulonglong2*)(Whh1 + rg * HH + k0);
            whh1p[g][c][0] = mul2c(v2.x, sg2); whh1p[g][c][1] = mul2c(v2.y, sg2);
        }
    }
    // own-gate (= sl) private data, pre-scaled
    const int og = 64 * sl + m;
    const float sq = (sl == 2) ? 1.0f : 0.5f;
    float4 wx = *(const float4*)(Wih0 + og * 4);
    wx.x *= sq; wx.y *= sq; wx.z *= sq; wx.w *= sq;
    const float  b0f  = (bih0[og] + bhh0[og]) * sq;
    const float  b1f  = (bih1[og] + bhh1[og]) * sq;
    const float wlreg = (sl < 2) ? Wlin[sl * 64 + m] : 0.0f;
    const float km = (sl == 2) ? 1.0f : 0.5f;
    const float kb = (sl == 2) ? 0.0f : 0.5f;

    float c0 = 0.f, c1 = 0.f, h0v = 0.f, h1v = 0.f;

    auto xsum = [&](int pi, int s) -> float {
        float4 xv = *(const float4*)&xinb[pi][s][0];
        float r = fmaf(wx.x, xv.x, b0f);
        r = fmaf(wx.y, xv.y, r);
        r = fmaf(wx.z, xv.z, r);
        return fmaf(wx.w, xv.w, r);
    };
    // heavy step s = 1..7: dual dot over h0(s-1), + h1(s-2) dot for s>1.
    auto step = [&](int s, float xs, const float* h0prev, const float* h1prev) {
        u64 a1[4] = {0,0,0,0}, a0[4] = {0,0,0,0};
        #pragma unroll
        for (int c = 0; c < 4; c++) {
            ulonglong2 hv = *(const ulonglong2*)(h0prev + 16 * c + 4 * sl);
            #pragma unroll
            for (int g = 0; g < 4; g++) {
                fma2(a0[g], hv.x, whh0p[g][c][0]); fma2(a0[g], hv.y, whh0p[g][c][1]);
                fma2(a1[g], hv.x, wih1p[g][c][0]); fma2(a1[g], hv.y, wih1p[g][c][1]);
            }
        }
        if (s > 1) {
            #pragma unroll
            for (int c = 0; c < 4; c++) {
                ulonglong2 hv = *(const ulonglong2*)(h1prev + 16 * c + 4 * sl);
                #pragma unroll
                for (int g = 0; g < 4; g++) {
                    fma2(a1[g], hv.x, whh1p[g][c][0]); fma2(a1[g], hv.y, whh1p[g][c][1]);
                }
            }
        }
        // P0(s) epilogue FIRST
        float arg0 = red4(a0[0], a0[1], a0[2], a0[3], sl) + xs;
        h0v = cell_from_act(fmaf(km, tanh_ap(arg0), kb), c0, false);
        if (sl == 0) { if (s == 7) h0z7[m] = h0v; else h0s[s & 1][m] = h0v; }
        // P1(s-1) epilogue
        float arg1 = red4(a1[0], a1[1], a1[2], a1[3], sl) + b1f;
        h1v = cell_from_act(fmaf(km, tanh_ap(arg1), kb), c1, s == 1);
        if (sl == 0) { if (s == 1) h1z[m] = h1v; else h1s[(s - 1) & 1][m] = h1v; }
    };
    // P1(7) of previous window (reads h0z7 + h1(6)=h1s[0]) + Wlin partial
    auto p1_last = [&]() {
        u64 a1[4] = {0,0,0,0};
        #pragma unroll
        for (int c = 0; c < 4; c++) {
            ulonglong2 hv = *(const ulonglong2*)(h0z7 + 16 * c + 4 * sl);
            ulonglong2 gv = *(const ulonglong2*)(h1s[0] + 16 * c + 4 * sl);
            #pragma unroll
            for (int g = 0; g < 4; g++) {
                fma2(a1[g], hv.x, wih1p[g][c][0]); fma2(a1[g], hv.y, wih1p[g][c][1]);
                fma2(a1[g], gv.x, whh1p[g][c][0]); fma2(a1[g], gv.y, whh1p[g][c][1]);
            }
        }
        float arg1 = red4(a1[0], a1[1], a1[2], a1[3], sl) + b1f;
        h1v = cell_from_act(fmaf(km, tanh_ap(arg1), kb), c1, false);
        float hb = __shfl_sync(0xffffffffu, h1v, lane & ~3);
        float pv = wlreg * hb;
        pv += __shfl_xor_sync(0xffffffffu, pv, 4);
        pv += __shfl_xor_sync(0xffffffffu, pv, 8);
        pv += __shfl_xor_sync(0xffffffffu, pv, 16);
        if (lane < 2) predpart[wid * 2 + lane] = pv;
    };

    __syncthreads();                 // staging done
    if (tid < 32) {                  // xin window 0 (pure traj)
        const int s = tid >> 2, f = tid & 3;
        xinb[0][s][f] = xin_value(trajs, preds, 0, s, f);
    }
    __syncthreads();

    // ===== prologue: P0(0, 0) -> h0z0 =====
    {
        float xs0 = xsum(0, 0);
        h0v = cell_from_act(fmaf(km, tanh_ap(xs0), kb), c0, true);
        if (sl == 0) h0z0[m] = h0v;
    }
    __syncthreads();

    for (int w = 0; w < NW; w++) {
        const int pw = w & 1;

        // ===== φ1: [P1(7,w-1) + predpart] + [P1(0,w) + P0(1,w)]
        {
            float xs = xsum(pw, 1);
            if (w > 0) p1_last();            // uses old c1, then step reinits it
            step(1, xs, h0z0, h0z0 /*unused*/);
        }
        __syncthreads();

        // ===== φ2: P1(1)+P0(2); side: warp6 finalizes pred[w-1]
        {
            float xs = xsum(pw, 2);
            step(2, xs, h0s[1], h1z);        // h0(1), h1(0)
            if (w > 0 && wid == 6 && lane < 2) {
                float d = blin_s[lane];
                #pragma unroll
                for (int k = 0; k < 8; k++) d += predpart[k * 2 + lane];
                const float prev = (w == 1) ? trajs[7 * 4 + 2 + lane]
                                            : preds[(w - 2) * 2 + lane];
                const float pr = prev + d;
                preds[(w - 1) * 2 + lane] = pr;
                out[(b * NW + (w - 1)) * 2 + lane] = pr;
            }
        }
        __syncthreads();

        // ===== φ3: P1(2)+P0(3); side: xin row7(w) + row6(w+1) (warp7, 8 lanes)
        {
            float xs = xsum(pw, 3);
            step(3, xs, h0s[0], h1s[1]);     // h0(2), h1(1)
            if (wid == 7 && lane < 8) {
                if (lane < 4)
                    xinb[pw][7][lane] = xin_value(trajs, preds, w, 7, lane);
                else if ((w + 1) < NW)
                    xinb[pw ^ 1][6][lane - 4] =
                        xin_value(trajs, preds, w + 1, 6, lane - 4);
            }
        }
        __syncthreads();

        // ===== φ4: P1(3)+P0(4); side: xin rows 0..5 of w+1 (warp5, 24 lanes)
        {
            float xs = xsum(pw, 4);
            step(4, xs, h0s[1], h1s[0]);     // h0(3), h1(2)
            if (wid == 5 && lane < 24 && (w + 1) < NW) {
                const int s = lane >> 2, f = lane & 3;
                xinb[pw ^ 1][s][f] = xin_value(trajs, preds, w + 1, s, f);
            }
        }
        __syncthreads();

        // ===== φ5: P1(4)+P0(5)
        {
            float xs = xsum(pw, 5);
            step(5, xs, h0s[0], h1s[1]);     // h0(4), h1(3)
        }
        __syncthreads();

        // ===== φ6: P1(5)+P0(6)
        {
            float xs = xsum(pw, 6);
            step(6, xs, h0s[1], h1s[0]);     // h0(5), h1(4)
        }
        __syncthreads();

        // ===== φ7: P1(6)+P0(7) [+ P0(0, w+1) -> h0z0]
        {
            float xs  = xsum(pw, 7);
            float xs0 = ((w + 1) < NW) ? xsum(pw ^ 1, 0) : 0.0f;
            step(7, xs, h0s[0], h1s[1]);     // h0(6), h1(5); stores h0z7, h1s[0]
            if ((w + 1) < NW) {
                float hz = cell_from_act(fmaf(km, tanh_ap(xs0), kb), c0, true);
                if (sl == 0) h0z0[m] = hz;
                h0v = hz;
            }
        }
        __syncthreads();
    }

    // ===== tail: P1(7, NW-1) + predpart, then finalize pred[NW-1] =====
    p1_last();
    __syncthreads();
    if (tid < 2) {
        float d = blin_s[tid];
        #pragma unroll
        for (int k = 0; k < 8; k++) d += predpart[k * 2 + tid];
        out[(b * NW + (NW - 1)) * 2 + tid] = preds[(NW - 2) * 2 + tid] + d;
    }
    // ---- final states: h[2,B,H] then c[2,B,H] (valid in sl==0 lanes) ----
    if (sl == 0) {
        const int base = BB * NW * 2;
        out[base + 0 * BB * HH + b * HH + m] = h0v;   // h0(7, NW-1)
        out[base + 1 * BB * HH + b * HH + m] = h1v;   // h1(7, NW-1)
        out[base + 2 * BB * HH + b * HH + m] = c0;
        out[base + 3 * BB * HH + b * HH + m] = c1;
    }
}

extern "C" void kernel_launch(void* const* d_in, const int* in_sizes, int n_in,
                              void* d_out, int out_size) {
    const float* traj = (const float*)d_in[0];
    const float* Wih0 = (const float*)d_in[1];
    const float* Whh0 = (const float*)d_in[2];
    const float* bih0 = (const float*)d_in[3];
    const float* bhh0 = (const float*)d_in[4];
    const float* Wih1 = (const float*)d_in[5];
    const float* Whh1 = (const float*)d_in[6];
    const float* bih1 = (const float*)d_in[7];
    const float* bhh1 = (const float*)d_in[8];
    const float* Wlin = (const float*)d_in[9];
    const float* blin = (const float*)d_in[10];

    or_lstm_kernel<<<BB, 256>>>(traj, Wih0, Whh0, bih0, bhh0,
                                Wih1, Whh1, bih1, bhh1,
                                Wlin, blin, (float*)d_out);
}